// round 2
// baseline (speedup 1.0000x reference)
#include <cuda_runtime.h>
#include <cuda_fp16.h>
#include <stdint.h>

// Problem constants
constexpr int BB = 128;    // batch
constexpr int TT = 512;    // seq len
constexpr int EE = 256;    // embed
constexpr int HH = 512;    // hidden
constexpr int GG = 2048;   // 4*H gates
constexpr int MR = BB * TT;  // 65536 rows

constexpr int NGROUP = 8;   // batch groups
constexpr int NSLICE = 16;  // CTAs per group
constexpr int BSUB   = 16;  // batch rows per group

// ---------------- static device scratch (allocation-free) ----------------
__device__ __half g_x16[(size_t)MR * EE];
__device__ __half g_h1 [(size_t)MR * HH];
__device__ float  g_xg [(size_t)MR * GG];     // 512 MB, reused across layers
__device__ __half g_wih0p[GG * EE];
__device__ __half g_wih1p[GG * HH];
__device__ __half g_whh0p[GG * HH];
__device__ __half g_whh1p[GG * HH];
__device__ float  g_bias0[GG];
__device__ float  g_bias1[GG];
__device__ __half g_hbuf[2 * BB * HH];        // double-buffered h exchange
__device__ float  g_hlast[BB * HH];
__device__ int    g_ctr[NGROUP];

// Column permutation: new index m -> original gate column n
// m = c*128 + q*32 + u  (c = CTA slice 0..15, q = gate 0..3, u = hidden-in-slice)
// n = q*512 + c*32 + u
__device__ __forceinline__ int perm_orig(int m) {
    int cc = m >> 7, l = m & 127, q = l >> 5, u = l & 31;
    return q * 512 + cc * 32 + u;
}

// ---------------- prep kernels ----------------
__global__ void k_conv_x(const float* __restrict__ x) {
    size_t i = (size_t)blockIdx.x * blockDim.x + threadIdx.x;
    if (i < (size_t)MR * EE) g_x16[i] = __float2half(x[i]);
}

__global__ void k_prep_w(const float* __restrict__ wih0, const float* __restrict__ whh0,
                         const float* __restrict__ wih1, const float* __restrict__ whh1) {
    int which = blockIdx.y;
    size_t i = (size_t)blockIdx.x * blockDim.x + threadIdx.x;
    const float* src; __half* dst; int K;
    if      (which == 0) { src = wih0; dst = g_wih0p; K = EE; }
    else if (which == 1) { src = whh0; dst = g_whh0p; K = HH; }
    else if (which == 2) { src = wih1; dst = g_wih1p; K = HH; }
    else                 { src = whh1; dst = g_whh1p; K = HH; }
    if (i >= (size_t)GG * K) return;
    int m = (int)(i / K), k = (int)(i % K);
    int n = perm_orig(m);
    dst[i] = __float2half(src[(size_t)n * K + k]);
}

__global__ void k_prep_b(const float* __restrict__ bih0, const float* __restrict__ bhh0,
                         const float* __restrict__ bih1, const float* __restrict__ bhh1) {
    int m = blockIdx.x * blockDim.x + threadIdx.x;
    if (m >= GG) return;
    int n = perm_orig(m);
    if (blockIdx.y == 0) g_bias0[m] = bih0[n] + bhh0[n];
    else                 g_bias1[m] = bih1[n] + bhh1[n];
}

__global__ void k_reset() {
    int i = blockIdx.x * blockDim.x + threadIdx.x;
    if (i < 2 * BB * HH / 2) ((uint32_t*)g_hbuf)[i] = 0u;
    if (i < NGROUP) g_ctr[i] = 0;
}

// ---------------- mma helper ----------------
__device__ __forceinline__ void mma16816(float* d, const uint32_t* a, uint32_t b0, uint32_t b1) {
    asm volatile(
        "mma.sync.aligned.m16n8k16.row.col.f32.f16.f16.f32 "
        "{%0,%1,%2,%3},{%4,%5,%6,%7},{%8,%9},{%0,%1,%2,%3};"
        : "+f"(d[0]), "+f"(d[1]), "+f"(d[2]), "+f"(d[3])
        : "r"(a[0]), "r"(a[1]), "r"(a[2]), "r"(a[3]), "r"(b0), "r"(b1));
}

// ---------------- xg GEMM: C[M, 2048] = A[M,K] @ Wp^T + bias ----------------
// BM=128, BN=64, BK=32, 256 threads (8 warps: 4 M x 2 N, warp tile 32x32)
template <int K>
__global__ __launch_bounds__(256, 1) void k_gemm_xg(int layer) {
    const __half* __restrict__ A = layer ? g_h1   : g_x16;
    const __half* __restrict__ W = layer ? g_wih1p : g_wih0p;
    const float*  __restrict__ bias = layer ? g_bias1 : g_bias0;

    __shared__ __align__(16) __half sA[128 * 40];
    __shared__ __align__(16) __half sB[64 * 40];

    int tid = threadIdx.x;
    int m0 = blockIdx.y * 128;
    int n0 = blockIdx.x * 64;
    int lane = tid & 31, warp = tid >> 5;
    int wm = warp & 3, wn = warp >> 2;
    int r = lane >> 2, tg = lane & 3;

    float acc[2][4][4] = {};

    for (int kt = 0; kt < K / 32; kt++) {
        // load A tile 128x32
#pragma unroll
        for (int i = 0; i < 2; i++) {
            int u = tid + i * 256;
            int row = u >> 2, c4 = u & 3;
            uint4 v = *(const uint4*)(A + (size_t)(m0 + row) * K + kt * 32 + c4 * 8);
            ((uint4*)sA)[row * 5 + c4] = v;
        }
        // load B tile 64x32
        {
            int row = tid >> 2, c4 = tid & 3;
            uint4 v = *(const uint4*)(W + (size_t)(n0 + row) * K + kt * 32 + c4 * 8);
            ((uint4*)sB)[row * 5 + c4] = v;
        }
        __syncthreads();
#pragma unroll
        for (int kk = 0; kk < 2; kk++) {
            int c0 = kk * 16 + tg * 2;
            uint32_t a[2][4];
#pragma unroll
            for (int mt = 0; mt < 2; mt++) {
                int rb = wm * 32 + mt * 16;
                a[mt][0] = *(const uint32_t*)&sA[(rb + r) * 40 + c0];
                a[mt][1] = *(const uint32_t*)&sA[(rb + r + 8) * 40 + c0];
                a[mt][2] = *(const uint32_t*)&sA[(rb + r) * 40 + c0 + 8];
                a[mt][3] = *(const uint32_t*)&sA[(rb + r + 8) * 40 + c0 + 8];
            }
#pragma unroll
            for (int nt = 0; nt < 4; nt++) {
                int nl = wn * 32 + nt * 8 + r;
                uint32_t b0 = *(const uint32_t*)&sB[nl * 40 + c0];
                uint32_t b1 = *(const uint32_t*)&sB[nl * 40 + c0 + 8];
#pragma unroll
                for (int mt = 0; mt < 2; mt++) mma16816(acc[mt][nt], a[mt], b0, b1);
            }
        }
        __syncthreads();
    }
    // epilogue: add bias, store fp32
#pragma unroll
    for (int mt = 0; mt < 2; mt++)
#pragma unroll
        for (int nt = 0; nt < 4; nt++) {
            int m = m0 + wm * 32 + mt * 16 + r;
            int n = n0 + wn * 32 + nt * 8 + tg * 2;
            float b0 = bias[n], b1 = bias[n + 1];
            float2 v0 = make_float2(acc[mt][nt][0] + b0, acc[mt][nt][1] + b1);
            float2 v1 = make_float2(acc[mt][nt][2] + b0, acc[mt][nt][3] + b1);
            *(float2*)&g_xg[(size_t)m * GG + n] = v0;
            *(float2*)&g_xg[(size_t)(m + 8) * GG + n] = v1;
        }
}

// ---------------- activations ----------------
__device__ __forceinline__ float sigm(float x) {
    return __fdividef(1.f, 1.f + __expf(-x));
}
__device__ __forceinline__ float tanh_f(float x) {
    float e = __expf(-2.f * fabsf(x));
    float t = __fdividef(1.f - e, 1.f + e);
    return copysignf(t, x);
}

// ---------------- persistent LSTM recurrence ----------------
// 128 CTAs = 8 groups x 16 slices. CTA (g,c): batch rows [g*16, g*16+16),
// hidden units [c*32, c*32+32), gate columns (permuted) [c*128, c*128+128).
// W_hh slice resident in SMEM. Per step: GEMM [16x512]@[512x128] via mma,
// + xg, activations, write h slice, group barrier.
constexpr int LSTM_SMEM = (128 * 520 + 16 * 520) * 2 + 16 * 132 * 4;  // 158208 B

template <int LAYER>
__global__ __launch_bounds__(128, 1) void k_lstm() {
    extern __shared__ __half smem[];
    __half* sW = smem;                        // [128][520]
    __half* sA = smem + 128 * 520;            // [16][520]
    float*  sG = (float*)(smem + 128 * 520 + 16 * 520);  // [16][132]

    const __half* __restrict__ Whh = LAYER ? g_whh1p : g_whh0p;

    int tid = threadIdx.x;
    int lane = tid & 31, warp = tid >> 5;
    int grp = blockIdx.x >> 4;
    int c = blockIdx.x & 15;
    int r = lane >> 2, tg = lane & 3;
    int jj = tid & 31;   // hidden-in-slice for activation phase
    int bq = tid >> 5;   // batch quad

    // load resident W slice: rows [c*128, c*128+128) of permuted W_hh
    {
        const uint4* src = (const uint4*)(Whh + (size_t)c * 128 * 512);
#pragma unroll
        for (int i = 0; i < 64; i++) {
            int u = tid + i * 128;
            int row = u >> 6, c4 = u & 63;
            ((uint4*)sW)[row * 65 + c4] = src[u];
        }
    }

    float cs[4] = {0.f, 0.f, 0.f, 0.f};
    const float* __restrict__ xgbase = g_xg + (size_t)c * 128;

    for (int t = 0; t < TT; t++) {
        // load h_prev [16 x 512] fp16 from exchange buffer (L1-bypass: peers wrote it)
        {
            const uint4* src = (const uint4*)(g_hbuf + ((size_t)((t & 1) * BB + grp * BSUB)) * HH);
#pragma unroll
            for (int i = 0; i < 8; i++) {
                int u = tid + i * 128;
                int row = u >> 6, c4 = u & 63;
                ((uint4*)sA)[row * 65 + c4] = __ldcv(src + u);
            }
        }
        __syncthreads();

        // GEMM: gates[16 x 128] = h_prev[16x512] @ Wslice^T ; warp owns 32 cols
        float acc[4][4] = {};
#pragma unroll 4
        for (int kt = 0; kt < 32; kt++) {
            int c0 = kt * 16 + tg * 2;
            uint32_t a[4];
            a[0] = *(const uint32_t*)&sA[r * 520 + c0];
            a[1] = *(const uint32_t*)&sA[(r + 8) * 520 + c0];
            a[2] = *(const uint32_t*)&sA[r * 520 + c0 + 8];
            a[3] = *(const uint32_t*)&sA[(r + 8) * 520 + c0 + 8];
#pragma unroll
            for (int nt = 0; nt < 4; nt++) {
                int nl = warp * 32 + nt * 8 + r;
                uint32_t b0 = *(const uint32_t*)&sW[nl * 520 + c0];
                uint32_t b1 = *(const uint32_t*)&sW[nl * 520 + c0 + 8];
                mma16816(acc[nt], a, b0, b1);
            }
        }
        // scatter gates to smem (cross-warp exchange: warp w computed gate w)
#pragma unroll
        for (int nt = 0; nt < 4; nt++) {
            int col = warp * 32 + nt * 8 + tg * 2;
            *(float2*)&sG[r * 132 + col] = make_float2(acc[nt][0], acc[nt][1]);
            *(float2*)&sG[(r + 8) * 132 + col] = make_float2(acc[nt][2], acc[nt][3]);
        }
        __syncthreads();

        // activations: thread handles hidden jj for 4 batch rows
#pragma unroll
        for (int q4 = 0; q4 < 4; q4++) {
            int b = bq * 4 + q4;
            int bgl = grp * BSUB + b;
            const float* xr = xgbase + ((size_t)bgl * TT + t) * GG;
            float ip = sG[b * 132 + jj]      + xr[jj];
            float fp = sG[b * 132 + 32 + jj] + xr[32 + jj];
            float gp = sG[b * 132 + 64 + jj] + xr[64 + jj];
            float op = sG[b * 132 + 96 + jj] + xr[96 + jj];
            float ig = sigm(ip), fg = sigm(fp), gv = tanh_f(gp), og = sigm(op);
            float cv = fg * cs[q4] + ig * gv;
            cs[q4] = cv;
            float hv = og * tanh_f(cv);
            __half hh = __float2half(hv);
            g_hbuf[((size_t)(((t + 1) & 1) * BB + bgl)) * HH + c * 32 + jj] = hh;
            if (LAYER == 0) g_h1[((size_t)bgl * TT + t) * HH + c * 32 + jj] = hh;
            if (LAYER == 1 && t == TT - 1) g_hlast[bgl * HH + c * 32 + jj] = hv;
        }

        // group barrier (release: fence all threads, then single arrive + spin)
        __threadfence();
        __syncthreads();
        if (tid == 0) {
            atomicAdd(&g_ctr[grp], 1);
            while (((volatile int*)g_ctr)[grp] < NSLICE * (t + 1)) {}
        }
        __syncthreads();
    }
}

// ---------------- final FC + sigmoid ----------------
__global__ void k_fc(const float* __restrict__ wfc, const float* __restrict__ bfc,
                     float* __restrict__ out) {
    int w = blockIdx.x * 4 + (threadIdx.x >> 5);
    int lane = threadIdx.x & 31;
    if (w < BB) {
        float s = 0.f;
        for (int k = lane; k < HH; k += 32) s += g_hlast[w * HH + k] * wfc[k];
#pragma unroll
        for (int o = 16; o; o >>= 1) s += __shfl_xor_sync(0xffffffffu, s, o);
        if (lane == 0) out[w] = 1.f / (1.f + __expf(-(s + bfc[0])));
    }
}

// ---------------- launch ----------------
extern "C" void kernel_launch(void* const* d_in, const int* in_sizes, int n_in,
                              void* d_out, int out_size) {
    const float* x    = (const float*)d_in[0];
    const float* wih0 = (const float*)d_in[1];
    const float* whh0 = (const float*)d_in[2];
    const float* bih0 = (const float*)d_in[3];
    const float* bhh0 = (const float*)d_in[4];
    const float* wih1 = (const float*)d_in[5];
    const float* whh1 = (const float*)d_in[6];
    const float* bih1 = (const float*)d_in[7];
    const float* bhh1 = (const float*)d_in[8];
    const float* wfc  = (const float*)d_in[9];
    const float* bfc  = (const float*)d_in[10];
    float* out = (float*)d_out;

    cudaFuncSetAttribute(k_lstm<0>, cudaFuncAttributeMaxDynamicSharedMemorySize, LSTM_SMEM);
    cudaFuncSetAttribute(k_lstm<1>, cudaFuncAttributeMaxDynamicSharedMemorySize, LSTM_SMEM);

    // prep: fp16 conversions + gate-column permutation
    k_conv_x<<<(MR * EE + 255) / 256, 256>>>(x);
    k_prep_w<<<dim3((GG * HH + 255) / 256, 4), 256>>>(wih0, whh0, wih1, whh1);
    k_prep_b<<<dim3((GG + 255) / 256, 2), 256>>>(bih0, bhh0, bih1, bhh1);

    // layer 1
    k_gemm_xg<EE><<<dim3(GG / 64, MR / 128), 256>>>(0);
    k_reset<<<256, 256>>>();
    k_lstm<0><<<NGROUP * NSLICE, 128, LSTM_SMEM>>>();

    // layer 2
    k_gemm_xg<HH><<<dim3(GG / 64, MR / 128), 256>>>(1);
    k_reset<<<256, 256>>>();
    k_lstm<1><<<NGROUP * NSLICE, 128, LSTM_SMEM>>>();

    // head
    k_fc<<<(BB + 3) / 4, 128>>>(wfc, bfc, out);
}

// round 3
// speedup vs baseline: 1.5620x; 1.5620x over previous
#include <cuda_runtime.h>
#include <cuda_fp16.h>
#include <stdint.h>

// Problem constants
constexpr int BB = 128;    // batch
constexpr int TT = 512;    // seq len
constexpr int EE = 256;    // embed
constexpr int HH = 512;    // hidden
constexpr int GG = 2048;   // 4*H gates
constexpr int MR = BB * TT;  // 65536 rows

constexpr int NGROUP = 8;   // batch groups
constexpr int NSLICE = 16;  // CTAs per group
constexpr int BSUB   = 16;  // batch rows per group

// ---------------- static device scratch (allocation-free) ----------------
__device__ __half g_x16[(size_t)MR * EE];
__device__ __half g_h1 [(size_t)MR * HH];
__device__ __half g_xg [(size_t)MR * GG];     // 256 MB fp16, reused across layers
__device__ __half g_wih0p[GG * EE];
__device__ __half g_wih1p[GG * HH];
__device__ __half g_whh0p[GG * HH];
__device__ __half g_whh1p[GG * HH];
__device__ float  g_bias0[GG];
__device__ float  g_bias1[GG];
__device__ __half g_hbuf[2 * BB * HH];        // double-buffered h exchange
__device__ float  g_hlast[BB * HH];
__device__ int    g_flag[NGROUP * NSLICE * 32]; // 128B-spread barrier flags

// Column permutation: new index m -> original gate column n
// m = c*128 + u*4 + q  (c = CTA slice 0..15, u = hidden-in-slice 0..31, q = gate 0..3)
// n = q*512 + c*32 + u   (gates interleaved per hidden unit -> uint2 xg loads)
__device__ __forceinline__ int perm_orig(int m) {
    int cc = m >> 7, l = m & 127, u = l >> 2, q = l & 3;
    return q * 512 + cc * 32 + u;
}

// ---------------- prep kernels ----------------
__global__ void k_conv_x(const float* __restrict__ x) {
    size_t i = (size_t)blockIdx.x * blockDim.x + threadIdx.x;
    if (i < (size_t)MR * EE) g_x16[i] = __float2half(x[i]);
}

__global__ void k_prep_w(const float* __restrict__ wih0, const float* __restrict__ whh0,
                         const float* __restrict__ wih1, const float* __restrict__ whh1) {
    int which = blockIdx.y;
    size_t i = (size_t)blockIdx.x * blockDim.x + threadIdx.x;
    const float* src; __half* dst; int K;
    if      (which == 0) { src = wih0; dst = g_wih0p; K = EE; }
    else if (which == 1) { src = whh0; dst = g_whh0p; K = HH; }
    else if (which == 2) { src = wih1; dst = g_wih1p; K = HH; }
    else                 { src = whh1; dst = g_whh1p; K = HH; }
    if (i >= (size_t)GG * K) return;
    int m = (int)(i / K), k = (int)(i % K);
    int n = perm_orig(m);
    dst[i] = __float2half(src[(size_t)n * K + k]);
}

__global__ void k_prep_b(const float* __restrict__ bih0, const float* __restrict__ bhh0,
                         const float* __restrict__ bih1, const float* __restrict__ bhh1) {
    int m = blockIdx.x * blockDim.x + threadIdx.x;
    if (m >= GG) return;
    int n = perm_orig(m);
    if (blockIdx.y == 0) g_bias0[m] = bih0[n] + bhh0[n];
    else                 g_bias1[m] = bih1[n] + bhh1[n];
}

__global__ void k_reset() {
    int i = blockIdx.x * blockDim.x + threadIdx.x;
    if (i < 2 * BB * HH / 2) ((uint32_t*)g_hbuf)[i] = 0u;
    if (i < NGROUP * NSLICE * 32) g_flag[i] = 0;
}

// ---------------- asm helpers ----------------
__device__ __forceinline__ void mma16816(float* d, const uint32_t* a, uint32_t b0, uint32_t b1) {
    asm volatile(
        "mma.sync.aligned.m16n8k16.row.col.f32.f16.f16.f32 "
        "{%0,%1,%2,%3},{%4,%5,%6,%7},{%8,%9},{%0,%1,%2,%3};"
        : "+f"(d[0]), "+f"(d[1]), "+f"(d[2]), "+f"(d[3])
        : "r"(a[0]), "r"(a[1]), "r"(a[2]), "r"(a[3]), "r"(b0), "r"(b1));
}

__device__ __forceinline__ void ldsm4(uint32_t& r0, uint32_t& r1, uint32_t& r2, uint32_t& r3,
                                      uint32_t addr) {
    asm volatile("ldmatrix.sync.aligned.m8n8.x4.shared.b16 {%0,%1,%2,%3}, [%4];"
                 : "=r"(r0), "=r"(r1), "=r"(r2), "=r"(r3) : "r"(addr));
}

__device__ __forceinline__ void cp16(uint32_t dst, const void* src) {
    asm volatile("cp.async.cg.shared.global [%0], [%1], 16;" :: "r"(dst), "l"(src));
}
__device__ __forceinline__ void cp_commit() { asm volatile("cp.async.commit_group;"); }
__device__ __forceinline__ void cp_wait0()  { asm volatile("cp.async.wait_group 0;"); }

// ---------------- xg GEMM: C[M, 2048] = A[M,K] @ Wp^T + bias (fp16 out) ----------------
// BM=128, BN=64, BK=32, 256 threads (8 warps: 4 M x 2 N, warp tile 32x32)
// 2-stage cp.async pipeline, ldmatrix fragments, 2 CTAs/SM.
template <int K>
__global__ __launch_bounds__(256, 2) void k_gemm_xg(int layer) {
    const __half* __restrict__ A = layer ? g_h1    : g_x16;
    const __half* __restrict__ W = layer ? g_wih1p : g_wih0p;
    const float*  __restrict__ bias = layer ? g_bias1 : g_bias0;

    __shared__ __align__(16) __half sA[2][128 * 40];
    __shared__ __align__(16) __half sB[2][64 * 40];

    int tid = threadIdx.x;
    int m0 = blockIdx.y * 128;
    int n0 = blockIdx.x * 64;
    int lane = tid & 31, warp = tid >> 5;
    int wm = warp & 3, wn = warp >> 2;
    int r = lane >> 2, tg = lane & 3;

    uint32_t sAu[2] = { (uint32_t)__cvta_generic_to_shared(sA[0]),
                        (uint32_t)__cvta_generic_to_shared(sA[1]) };
    uint32_t sBu[2] = { (uint32_t)__cvta_generic_to_shared(sB[0]),
                        (uint32_t)__cvta_generic_to_shared(sB[1]) };

    // cp.async source/dst indices
    int ar0 = tid >> 2, ac4 = tid & 3;                 // A: 2 chunks per thread
    int br0 = tid >> 2, bc4 = tid & 3;                 // B: 1 chunk per thread

    // ldmatrix lane offsets (bytes)
    uint32_t laneA = (uint32_t)(((lane & 15) * 40 + ((lane >> 4) << 3)) << 1);
    int bnn = wn * 32 + ((lane >> 4) & 1) * 8 + (lane & 7);
    uint32_t laneB = (uint32_t)((bnn * 40 + ((lane >> 3) & 1) * 8) << 1);

    float acc[2][4][4] = {};
    constexpr int KT = K / 32;

    // prefetch stage 0
    {
#pragma unroll
        for (int i = 0; i < 2; i++) {
            int row = ar0 + i * 64;
            cp16(sAu[0] + (uint32_t)((row * 5 + ac4) * 16),
                 A + (size_t)(m0 + row) * K + ac4 * 8);
        }
        cp16(sBu[0] + (uint32_t)((br0 * 5 + bc4) * 16),
             W + (size_t)(n0 + br0) * K + bc4 * 8);
        cp_commit();
    }

    for (int kt = 0; kt < KT; kt++) {
        cp_wait0();
        __syncthreads();
        if (kt + 1 < KT) {
            int st = (kt + 1) & 1;
#pragma unroll
            for (int i = 0; i < 2; i++) {
                int row = ar0 + i * 64;
                cp16(sAu[st] + (uint32_t)((row * 5 + ac4) * 16),
                     A + (size_t)(m0 + row) * K + (kt + 1) * 32 + ac4 * 8);
            }
            cp16(sBu[st] + (uint32_t)((br0 * 5 + bc4) * 16),
                 W + (size_t)(n0 + br0) * K + (kt + 1) * 32 + bc4 * 8);
            cp_commit();
        }
        int st = kt & 1;
#pragma unroll
        for (int kk = 0; kk < 2; kk++) {
            uint32_t kko = (uint32_t)(kk * 32);
            uint32_t a[2][4];
#pragma unroll
            for (int mt = 0; mt < 2; mt++) {
                uint32_t addr = sAu[st] + (uint32_t)(((wm * 32 + mt * 16) * 40) << 1) + laneA + kko;
                ldsm4(a[mt][0], a[mt][1], a[mt][2], a[mt][3], addr);
            }
            uint32_t p0, p1, p2, p3, q0, q1, q2, q3;
            ldsm4(p0, p1, p2, p3, sBu[st] + laneB + kko);
            ldsm4(q0, q1, q2, q3, sBu[st] + laneB + (uint32_t)((16 * 40) << 1) + kko);
#pragma unroll
            for (int mt = 0; mt < 2; mt++) {
                mma16816(acc[mt][0], a[mt], p0, p1);
                mma16816(acc[mt][1], a[mt], p2, p3);
                mma16816(acc[mt][2], a[mt], q0, q1);
                mma16816(acc[mt][3], a[mt], q2, q3);
            }
        }
        __syncthreads();
    }

    // epilogue: add bias, store fp16
#pragma unroll
    for (int mt = 0; mt < 2; mt++)
#pragma unroll
        for (int nt = 0; nt < 4; nt++) {
            int m = m0 + wm * 32 + mt * 16 + r;
            int n = n0 + wn * 32 + nt * 8 + tg * 2;
            float b0 = bias[n], b1 = bias[n + 1];
            __half2 v0 = __floats2half2_rn(acc[mt][nt][0] + b0, acc[mt][nt][1] + b1);
            __half2 v1 = __floats2half2_rn(acc[mt][nt][2] + b0, acc[mt][nt][3] + b1);
            *(__half2*)&g_xg[(size_t)m * GG + n] = v0;
            *(__half2*)&g_xg[(size_t)(m + 8) * GG + n] = v1;
        }
}

// ---------------- activations ----------------
__device__ __forceinline__ float sigm(float x) {
    return __fdividef(1.f, 1.f + __expf(-x));
}
__device__ __forceinline__ float tanh_f(float x) {
    float e = __expf(-2.f * fabsf(x));
    float t = __fdividef(1.f - e, 1.f + e);
    return copysignf(t, x);
}

// ---------------- persistent LSTM recurrence ----------------
// 128 CTAs = 8 groups x 16 slices. CTA (g,c): batch rows [g*16, g*16+16),
// hidden units [c*32, c*32+32), permuted gate cols [c*128, c*128+128).
// W_hh slice resident in SMEM. Per step: ldmatrix+mma GEMM [16x512]@[512x128],
// xg prefetched into regs at step top, release/acquire flag barrier.
constexpr int LSTM_SMEM = (128 * 520 + 16 * 520) * 2 + 16 * 132 * 4;  // 158208 B

template <int LAYER>
__global__ __launch_bounds__(128, 1) void k_lstm() {
    extern __shared__ __half smem[];
    __half* sW = smem;                                   // [128][520]
    __half* sA = smem + 128 * 520;                       // [16][520]
    float*  sG = (float*)(smem + 144 * 520);             // [16][132]

    const __half* __restrict__ Whh = LAYER ? g_whh1p : g_whh0p;

    int tid = threadIdx.x;
    int lane = tid & 31, warp = tid >> 5;
    int grp = blockIdx.x >> 4;
    int c = blockIdx.x & 15;
    int r = lane >> 2, tg = lane & 3;
    int jj = tid & 31;   // hidden-in-slice for activation phase
    int bq = tid >> 5;   // batch quad

    // load resident W slice: rows [c*128, c*128+128) of permuted W_hh
    {
        const uint4* src = (const uint4*)(Whh + (size_t)c * 128 * 512);
#pragma unroll
        for (int i = 0; i < 64; i++) {
            int u = tid + i * 128;
            int row = u >> 6, c4 = u & 63;
            ((uint4*)sW)[row * 65 + c4] = src[u];
        }
    }

    // ldmatrix lane bases
    uint32_t sA_u = (uint32_t)__cvta_generic_to_shared(sA);
    uint32_t sW_u = (uint32_t)__cvta_generic_to_shared(sW);
    uint32_t aAddr = sA_u + (uint32_t)((((lane & 15) * 520) + ((lane >> 4) << 3)) << 1);
    int bn = warp * 32 + ((lane >> 4) & 1) * 8 + (lane & 7);
    uint32_t bAddr0 = sW_u + (uint32_t)(((bn * 520) + ((lane >> 3) & 1) * 8) << 1);
    uint32_t bAddr1 = bAddr0 + (uint32_t)((16 * 520) << 1);

    float cs[4] = {0.f, 0.f, 0.f, 0.f};
    int bgl0 = grp * BSUB + bq * 4;
    int* myflag = &g_flag[(grp * NSLICE + c) * 32];
    int* pollflag = &g_flag[(grp * NSLICE + (tid & 15)) * 32];

    for (int t = 0; t < TT; t++) {
        // prefetch xg for this step (fp16, gates interleaved per hidden unit)
        uint2 xgv[4];
#pragma unroll
        for (int q4 = 0; q4 < 4; q4++) {
            const __half* xp = g_xg + ((size_t)(bgl0 + q4) * TT + t) * GG + c * 128 + jj * 4;
            xgv[q4] = __ldcs((const uint2*)xp);
        }

        // load h_prev [16 x 512] fp16 from exchange buffer (L1-bypass)
        {
            const uint4* src = (const uint4*)(g_hbuf + ((size_t)((t & 1) * BB + grp * BSUB)) * HH);
#pragma unroll
            for (int i = 0; i < 8; i++) {
                int u = tid + i * 128;
                int row = u >> 6, c4 = u & 63;
                ((uint4*)sA)[row * 65 + c4] = __ldcv(src + u);
            }
        }
        __syncthreads();

        // GEMM: gates[16 x 128] = h_prev[16x512] @ Wslice^T ; warp owns 32 cols
        float acc[4][4] = {};
#pragma unroll
        for (int kt = 0; kt < 32; kt++) {
            uint32_t ko = (uint32_t)((kt * 16) << 1);
            uint32_t a[4];
            uint32_t p0, p1, p2, p3, q0, q1, q2, q3;
            ldsm4(a[0], a[1], a[2], a[3], aAddr + ko);
            ldsm4(p0, p1, p2, p3, bAddr0 + ko);
            ldsm4(q0, q1, q2, q3, bAddr1 + ko);
            mma16816(acc[0], a, p0, p1);
            mma16816(acc[1], a, p2, p3);
            mma16816(acc[2], a, q0, q1);
            mma16816(acc[3], a, q2, q3);
        }
        // scatter gates to smem (cross-warp exchange)
#pragma unroll
        for (int nt = 0; nt < 4; nt++) {
            int col = warp * 32 + nt * 8 + tg * 2;
            *(float2*)&sG[r * 132 + col]       = make_float2(acc[nt][0], acc[nt][1]);
            *(float2*)&sG[(r + 8) * 132 + col] = make_float2(acc[nt][2], acc[nt][3]);
        }
        __syncthreads();

        // activations: thread handles hidden jj for 4 batch rows, gates i,f,g,o packed
#pragma unroll
        for (int q4 = 0; q4 < 4; q4++) {
            int b = bq * 4 + q4;
            int bgl = bgl0 + q4;
            float4 gv = *(float4*)&sG[b * 132 + jj * 4];
            __half2 x01 = *(__half2*)&xgv[q4].x;   // i, f
            __half2 x23 = *(__half2*)&xgv[q4].y;   // g, o
            float ip = gv.x + __low2float(x01);
            float fp = gv.y + __high2float(x01);
            float gp = gv.z + __low2float(x23);
            float op = gv.w + __high2float(x23);
            float ig = sigm(ip), fg = sigm(fp), gvv = tanh_f(gp), og = sigm(op);
            float cv = fg * cs[q4] + ig * gvv;
            cs[q4] = cv;
            float hv = og * tanh_f(cv);
            __half hh = __float2half(hv);
            g_hbuf[((size_t)(((t + 1) & 1) * BB + bgl)) * HH + c * 32 + jj] = hh;
            if (LAYER == 0) g_h1[((size_t)bgl * TT + t) * HH + c * 32 + jj] = hh;
            if (LAYER == 1 && t == TT - 1) g_hlast[bgl * HH + c * 32 + jj] = hv;
        }

        // group barrier: release flag, 16 parallel acquire pollers
        __syncthreads();
        if (tid == 0) {
            asm volatile("st.release.gpu.global.s32 [%0], %1;"
                         :: "l"(myflag), "r"(t + 1) : "memory");
        }
        if (tid < 16) {
            int v;
            do {
                asm volatile("ld.acquire.gpu.global.s32 %0, [%1];"
                             : "=r"(v) : "l"(pollflag) : "memory");
            } while (v <= t);
        }
        __syncthreads();
    }
}

// ---------------- final FC + sigmoid ----------------
__global__ void k_fc(const float* __restrict__ wfc, const float* __restrict__ bfc,
                     float* __restrict__ out) {
    int w = blockIdx.x * 4 + (threadIdx.x >> 5);
    int lane = threadIdx.x & 31;
    if (w < BB) {
        float s = 0.f;
        for (int k = lane; k < HH; k += 32) s += g_hlast[w * HH + k] * wfc[k];
#pragma unroll
        for (int o = 16; o; o >>= 1) s += __shfl_xor_sync(0xffffffffu, s, o);
        if (lane == 0) out[w] = 1.f / (1.f + __expf(-(s + bfc[0])));
    }
}

// ---------------- launch ----------------
extern "C" void kernel_launch(void* const* d_in, const int* in_sizes, int n_in,
                              void* d_out, int out_size) {
    const float* x    = (const float*)d_in[0];
    const float* wih0 = (const float*)d_in[1];
    const float* whh0 = (const float*)d_in[2];
    const float* bih0 = (const float*)d_in[3];
    const float* bhh0 = (const float*)d_in[4];
    const float* wih1 = (const float*)d_in[5];
    const float* whh1 = (const float*)d_in[6];
    const float* bih1 = (const float*)d_in[7];
    const float* bhh1 = (const float*)d_in[8];
    const float* wfc  = (const float*)d_in[9];
    const float* bfc  = (const float*)d_in[10];
    float* out = (float*)d_out;

    cudaFuncSetAttribute(k_lstm<0>, cudaFuncAttributeMaxDynamicSharedMemorySize, LSTM_SMEM);
    cudaFuncSetAttribute(k_lstm<1>, cudaFuncAttributeMaxDynamicSharedMemorySize, LSTM_SMEM);

    // prep: fp16 conversions + gate-column permutation
    k_conv_x<<<(MR * EE + 255) / 256, 256>>>(x);
    k_prep_w<<<dim3((GG * HH + 255) / 256, 4), 256>>>(wih0, whh0, wih1, whh1);
    k_prep_b<<<dim3((GG + 255) / 256, 2), 256>>>(bih0, bhh0, bih1, bhh1);

    // layer 1
    k_gemm_xg<EE><<<dim3(GG / 64, MR / 128), 256>>>(0);
    k_reset<<<256, 256>>>();
    k_lstm<0><<<NGROUP * NSLICE, 128, LSTM_SMEM>>>();

    // layer 2
    k_gemm_xg<HH><<<dim3(GG / 64, MR / 128), 256>>>(1);
    k_reset<<<256, 256>>>();
    k_lstm<1><<<NGROUP * NSLICE, 128, LSTM_SMEM>>>();

    // head
    k_fc<<<(BB + 3) / 4, 128>>>(wfc, bfc, out);
}

// round 4
// speedup vs baseline: 1.5855x; 1.0150x over previous
#include <cuda_runtime.h>
#include <cuda_fp16.h>
#include <stdint.h>

// Problem constants
constexpr int BB = 128;    // batch
constexpr int TT = 512;    // seq len
constexpr int EE = 256;    // embed
constexpr int HH = 512;    // hidden
constexpr int GG = 2048;   // 4*H gates
constexpr int MR = BB * TT;  // 65536 rows

constexpr int NGROUP = 8;   // batch groups
constexpr int NSLICE = 16;  // CTAs per group
constexpr int BSUB   = 16;  // batch rows per group

// ---------------- static device scratch (allocation-free) ----------------
__device__ __half g_x16[(size_t)MR * EE];
__device__ __half g_h1 [(size_t)MR * HH];
__device__ __half g_xg [(size_t)MR * GG];     // 256 MB fp16, reused across layers
__device__ __half g_wih0p[GG * EE];
__device__ __half g_wih1p[GG * HH];
__device__ __half g_whh0p[GG * HH];
__device__ __half g_whh1p[GG * HH];
__device__ float  g_bias0[GG];
__device__ float  g_bias1[GG];
__device__ __half g_hbuf[2 * BB * HH];        // double-buffered h exchange
__device__ float  g_hlast[BB * HH];
__device__ int    g_flag[NGROUP * NSLICE * 32]; // 128B-spread barrier flags

// Column permutation: new index m -> original gate column n
// m = c*128 + u*4 + q  (c = CTA slice 0..15, u = hidden-in-slice 0..31, q = gate 0..3)
// n = q*512 + c*32 + u   (gates interleaved per hidden unit -> uint2 xg loads)
__device__ __forceinline__ int perm_orig(int m) {
    int cc = m >> 7, l = m & 127, u = l >> 2, q = l & 3;
    return q * 512 + cc * 32 + u;
}

// ---------------- prep kernels ----------------
__global__ void k_conv_x(const float* __restrict__ x) {
    size_t i = (size_t)blockIdx.x * blockDim.x + threadIdx.x;
    if (i < (size_t)MR * EE) g_x16[i] = __float2half(x[i]);
}

__global__ void k_prep_w(const float* __restrict__ wih0, const float* __restrict__ whh0,
                         const float* __restrict__ wih1, const float* __restrict__ whh1) {
    int which = blockIdx.y;
    size_t i = (size_t)blockIdx.x * blockDim.x + threadIdx.x;
    const float* src; __half* dst; int K;
    if      (which == 0) { src = wih0; dst = g_wih0p; K = EE; }
    else if (which == 1) { src = whh0; dst = g_whh0p; K = HH; }
    else if (which == 2) { src = wih1; dst = g_wih1p; K = HH; }
    else                 { src = whh1; dst = g_whh1p; K = HH; }
    if (i >= (size_t)GG * K) return;
    int m = (int)(i / K), k = (int)(i % K);
    int n = perm_orig(m);
    dst[i] = __float2half(src[(size_t)n * K + k]);
}

__global__ void k_prep_b(const float* __restrict__ bih0, const float* __restrict__ bhh0,
                         const float* __restrict__ bih1, const float* __restrict__ bhh1) {
    int m = blockIdx.x * blockDim.x + threadIdx.x;
    if (m >= GG) return;
    int n = perm_orig(m);
    if (blockIdx.y == 0) g_bias0[m] = bih0[n] + bhh0[n];
    else                 g_bias1[m] = bih1[n] + bhh1[n];
}

__global__ void k_reset() {
    int i = blockIdx.x * blockDim.x + threadIdx.x;
    if (i < 2 * BB * HH / 2) ((uint32_t*)g_hbuf)[i] = 0u;
    if (i < NGROUP * NSLICE * 32) g_flag[i] = 0;
}

// ---------------- asm helpers ----------------
__device__ __forceinline__ void mma16816(float* d, const uint32_t* a, uint32_t b0, uint32_t b1) {
    asm volatile(
        "mma.sync.aligned.m16n8k16.row.col.f32.f16.f16.f32 "
        "{%0,%1,%2,%3},{%4,%5,%6,%7},{%8,%9},{%0,%1,%2,%3};"
        : "+f"(d[0]), "+f"(d[1]), "+f"(d[2]), "+f"(d[3])
        : "r"(a[0]), "r"(a[1]), "r"(a[2]), "r"(a[3]), "r"(b0), "r"(b1));
}

__device__ __forceinline__ void ldsm4(uint32_t& r0, uint32_t& r1, uint32_t& r2, uint32_t& r3,
                                      uint32_t addr) {
    asm volatile("ldmatrix.sync.aligned.m8n8.x4.shared.b16 {%0,%1,%2,%3}, [%4];"
                 : "=r"(r0), "=r"(r1), "=r"(r2), "=r"(r3) : "r"(addr));
}

__device__ __forceinline__ void cp16(uint32_t dst, const void* src) {
    asm volatile("cp.async.cg.shared.global [%0], [%1], 16;" :: "r"(dst), "l"(src));
}
__device__ __forceinline__ void cp_commit() { asm volatile("cp.async.commit_group;"); }
__device__ __forceinline__ void cp_wait0()  { asm volatile("cp.async.wait_group 0;"); }

__device__ __forceinline__ float tanhfast(float x) {
    float y;
    asm("tanh.approx.f32 %0, %1;" : "=f"(y) : "f"(x));
    return y;
}
__device__ __forceinline__ float sigm(float x) {
    return fmaf(0.5f, tanhfast(0.5f * x), 0.5f);
}

// ---------------- xg GEMM: C[M, 2048] = A[M,K] @ Wp^T + bias (fp16 out) ----------------
// BM=128, BN=64, BK=64, 256 threads (8 warps: 4 M x 2 N, warp tile 32x32)
// 2-stage cp.async pipeline (BK=64 per stage), ldmatrix fragments, 2 CTAs/SM.
constexpr int GEMM_SMEM = 2 * (128 * 72 + 64 * 72) * 2;  // 55296 B

template <int K>
__global__ __launch_bounds__(256, 2) void k_gemm_xg(int layer) {
    const __half* __restrict__ A = layer ? g_h1    : g_x16;
    const __half* __restrict__ W = layer ? g_wih1p : g_wih0p;
    const float*  __restrict__ bias = layer ? g_bias1 : g_bias0;

    extern __shared__ __align__(16) __half gsm[];
    __half* sA[2] = { gsm,               gsm + (128 + 64) * 72 };
    __half* sB[2] = { gsm + 128 * 72,    gsm + (128 + 64) * 72 + 128 * 72 };

    int tid = threadIdx.x;
    int m0 = blockIdx.y * 128;
    int n0 = blockIdx.x * 64;
    int lane = tid & 31, warp = tid >> 5;
    int wm = warp & 3, wn = warp >> 2;
    int r = lane >> 2, tg = lane & 3;

    uint32_t sAu[2] = { (uint32_t)__cvta_generic_to_shared(sA[0]),
                        (uint32_t)__cvta_generic_to_shared(sA[1]) };
    uint32_t sBu[2] = { (uint32_t)__cvta_generic_to_shared(sB[0]),
                        (uint32_t)__cvta_generic_to_shared(sB[1]) };

    // cp.async indices: A 128x64 (8 chunks/row, 2 thr/row), B 64x64 (8 chunks/row, 4 thr/row)
    int arow = tid >> 1, ac = (tid & 1) * 4;
    int brow = tid >> 2, bc = (tid & 3) * 2;

    // ldmatrix lane offsets (bytes), stride 72 halves = 144 B
    uint32_t laneA = (uint32_t)(((lane & 15) * 72 + ((lane >> 4) << 3)) << 1);
    int bnn = wn * 32 + ((lane >> 4) & 1) * 8 + (lane & 7);
    uint32_t laneB = (uint32_t)((bnn * 72 + ((lane >> 3) & 1) * 8) << 1);

    float acc[2][4][4] = {};
    constexpr int KT = K / 64;

    auto load_stage = [&](int st, int kt) {
#pragma unroll
        for (int i = 0; i < 4; i++)
            cp16(sAu[st] + (uint32_t)((arow * 72 + (ac + i) * 8) * 2),
                 A + (size_t)(m0 + arow) * K + kt * 64 + (ac + i) * 8);
#pragma unroll
        for (int i = 0; i < 2; i++)
            cp16(sBu[st] + (uint32_t)((brow * 72 + (bc + i) * 8) * 2),
                 W + (size_t)(n0 + brow) * K + kt * 64 + (bc + i) * 8);
        cp_commit();
    };

    load_stage(0, 0);

    for (int kt = 0; kt < KT; kt++) {
        cp_wait0();
        __syncthreads();
        if (kt + 1 < KT) load_stage((kt + 1) & 1, kt + 1);
        int st = kt & 1;
#pragma unroll
        for (int kk = 0; kk < 4; kk++) {
            uint32_t kko = (uint32_t)(kk * 32);
            uint32_t a[2][4];
#pragma unroll
            for (int mt = 0; mt < 2; mt++) {
                uint32_t addr = sAu[st] + (uint32_t)(((wm * 32 + mt * 16) * 72) << 1) + laneA + kko;
                ldsm4(a[mt][0], a[mt][1], a[mt][2], a[mt][3], addr);
            }
            uint32_t p0, p1, p2, p3, q0, q1, q2, q3;
            ldsm4(p0, p1, p2, p3, sBu[st] + laneB + kko);
            ldsm4(q0, q1, q2, q3, sBu[st] + laneB + (uint32_t)((16 * 72) << 1) + kko);
#pragma unroll
            for (int mt = 0; mt < 2; mt++) {
                mma16816(acc[mt][0], a[mt], p0, p1);
                mma16816(acc[mt][1], a[mt], p2, p3);
                mma16816(acc[mt][2], a[mt], q0, q1);
                mma16816(acc[mt][3], a[mt], q2, q3);
            }
        }
        __syncthreads();
    }

    // epilogue: add bias, store fp16
#pragma unroll
    for (int mt = 0; mt < 2; mt++)
#pragma unroll
        for (int nt = 0; nt < 4; nt++) {
            int m = m0 + wm * 32 + mt * 16 + r;
            int n = n0 + wn * 32 + nt * 8 + tg * 2;
            float b0 = bias[n], b1 = bias[n + 1];
            __half2 v0 = __floats2half2_rn(acc[mt][nt][0] + b0, acc[mt][nt][1] + b1);
            __half2 v1 = __floats2half2_rn(acc[mt][nt][2] + b0, acc[mt][nt][3] + b1);
            *(__half2*)&g_xg[(size_t)m * GG + n] = v0;
            *(__half2*)&g_xg[(size_t)(m + 8) * GG + n] = v1;
        }
}

// ---------------- persistent LSTM recurrence ----------------
// 128 CTAs = 8 groups x 16 slices, 256 threads each (8 warps, 16 gate cols/warp).
// CTA (g,c): batch rows [g*16, g*16+16), hidden [c*32, c*32+32),
// permuted gate cols [c*128, c*128+128). W_hh slice resident in SMEM.
// smem layout (halves): sW [128*520] | sA [16*520] | sG float[16*132] | sH [16*32]
constexpr int LSTM_SMEM = (128 * 520 + 16 * 520) * 2 + 16 * 132 * 4 + 16 * 32 * 2; // 159232 B

template <int LAYER>
__global__ __launch_bounds__(256, 1) void k_lstm() {
    extern __shared__ __half smem[];
    __half* sW = smem;                                   // [128][520]
    __half* sA = smem + 128 * 520;                       // [16][520]
    float*  sG = (float*)(smem + 144 * 520);             // [16][132]
    __half* sH = (__half*)(sG + 16 * 132);               // [16][32]

    const __half* __restrict__ Whh = LAYER ? g_whh1p : g_whh0p;

    int tid = threadIdx.x;
    int lane = tid & 31, warp = tid >> 5;
    int grp = blockIdx.x >> 4;
    int c = blockIdx.x & 15;
    int r = lane >> 2, tg = lane & 3;
    int jj = tid & 31;   // hidden-in-slice for activation phase
    int b2 = tid >> 5;   // row pair index (0..7)

    // load resident W slice: rows [c*128, c*128+128) of permuted W_hh
    {
        const uint4* src = (const uint4*)(Whh + (size_t)c * 128 * 512);
#pragma unroll
        for (int i = 0; i < 32; i++) {
            int u = tid + i * 256;
            int row = u >> 6, c4 = u & 63;
            ((uint4*)sW)[row * 65 + c4] = src[u];
        }
    }

    // ldmatrix lane bases
    uint32_t sA_u = (uint32_t)__cvta_generic_to_shared(sA);
    uint32_t sW_u = (uint32_t)__cvta_generic_to_shared(sW);
    uint32_t aAddr = sA_u + (uint32_t)((((lane & 15) * 520) + ((lane >> 4) << 3)) << 1);
    int bn = warp * 16 + ((lane >> 4) & 1) * 8 + (lane & 7);
    uint32_t bAddr = sW_u + (uint32_t)(((bn * 520) + ((lane >> 3) & 1) * 8) << 1);

    float cs[2] = {0.f, 0.f};
    int* myflag = &g_flag[(grp * NSLICE + c) * 32];
    int* pollflag = (tid >= 64 && tid < 80) ? &g_flag[(grp * NSLICE + (tid - 64)) * 32] : myflag;

    for (int t = 0; t < TT; t++) {
        // prefetch xg for this step (fp16, gates i,f,g,o interleaved per hidden unit)
        uint2 xgv[2];
#pragma unroll
        for (int q = 0; q < 2; q++) {
            int bgl = grp * BSUB + b2 * 2 + q;
            const __half* xp = g_xg + ((size_t)bgl * TT + t) * GG + c * 128 + jj * 4;
            xgv[q] = __ldcs((const uint2*)xp);
        }

        // load h_prev [16 x 512] fp16 from exchange buffer (L1-bypass: peers wrote it)
        {
            const uint4* src = (const uint4*)(g_hbuf + ((size_t)((t & 1) * BB + grp * BSUB)) * HH);
#pragma unroll
            for (int i = 0; i < 4; i++) {
                int u = tid + i * 256;
                int row = u >> 6, c4 = u & 63;
                ((uint4*)sA)[row * 65 + c4] = __ldcv(src + u);
            }
        }
        __syncthreads();

        // GEMM: gates[16 x 128] = h_prev[16x512] @ Wslice^T ; warp owns 16 cols
        float acc[2][4] = {};
#pragma unroll 4
        for (int kt = 0; kt < 32; kt++) {
            uint32_t ko = (uint32_t)((kt * 16) << 1);
            uint32_t a[4];
            uint32_t p0, p1, p2, p3;
            ldsm4(a[0], a[1], a[2], a[3], aAddr + ko);
            ldsm4(p0, p1, p2, p3, bAddr + ko);
            mma16816(acc[0], a, p0, p1);
            mma16816(acc[1], a, p2, p3);
        }
        // scatter gates to smem (cross-warp exchange)
#pragma unroll
        for (int nt = 0; nt < 2; nt++) {
            int col = warp * 16 + nt * 8 + tg * 2;
            *(float2*)&sG[r * 132 + col]       = make_float2(acc[nt][0], acc[nt][1]);
            *(float2*)&sG[(r + 8) * 132 + col] = make_float2(acc[nt][2], acc[nt][3]);
        }
        __syncthreads();

        // activations: thread handles hidden jj for 2 batch rows, gates i,f,g,o packed
#pragma unroll
        for (int q = 0; q < 2; q++) {
            int b = b2 * 2 + q;
            float4 gv = *(float4*)&sG[b * 132 + jj * 4];
            __half2 x01 = *(__half2*)&xgv[q].x;   // i, f
            __half2 x23 = *(__half2*)&xgv[q].y;   // g, o
            float ip = gv.x + __low2float(x01);
            float fp = gv.y + __high2float(x01);
            float gp = gv.z + __low2float(x23);
            float op = gv.w + __high2float(x23);
            float ig = sigm(ip), fg = sigm(fp), gvv = tanhfast(gp), og = sigm(op);
            float cv = fg * cs[q] + ig * gvv;
            cs[q] = cv;
            float hv = og * tanhfast(cv);
            sH[b * 32 + jj] = __float2half(hv);
        }
        __syncthreads();

        // publish h (64 writer threads, vectorized) + release; pollers overlap
        if (tid < 64) {
            int row16 = tid >> 2, chunk = tid & 3;
            uint4 hv4 = *(uint4*)&sH[row16 * 32 + chunk * 8];
            int bgl = grp * BSUB + row16;
            *(uint4*)&g_hbuf[((size_t)(((t + 1) & 1) * BB + bgl)) * HH + c * 32 + chunk * 8] = hv4;
            if (LAYER == 0)
                *(uint4*)&g_h1[((size_t)bgl * TT + t) * HH + c * 32 + chunk * 8] = hv4;
            if (LAYER == 1 && t == TT - 1) {
                const __half* hp = &sH[row16 * 32 + chunk * 8];
                float* dp = &g_hlast[bgl * HH + c * 32 + chunk * 8];
#pragma unroll
                for (int e = 0; e < 8; e++) dp[e] = __half2float(hp[e]);
            }
            asm volatile("bar.sync 1, 64;");
            if (tid == 0)
                asm volatile("st.release.gpu.global.s32 [%0], %1;"
                             :: "l"(myflag), "r"(t + 1) : "memory");
        } else if (tid < 80) {
            int v;
            do {
                asm volatile("ld.acquire.gpu.global.s32 %0, [%1];"
                             : "=r"(v) : "l"(pollflag) : "memory");
            } while (v <= t);
        }
        __syncthreads();
    }
}

// ---------------- final FC + sigmoid ----------------
__global__ void k_fc(const float* __restrict__ wfc, const float* __restrict__ bfc,
                     float* __restrict__ out) {
    int w = blockIdx.x * 4 + (threadIdx.x >> 5);
    int lane = threadIdx.x & 31;
    if (w < BB) {
        float s = 0.f;
        for (int k = lane; k < HH; k += 32) s += g_hlast[w * HH + k] * wfc[k];
#pragma unroll
        for (int o = 16; o; o >>= 1) s += __shfl_xor_sync(0xffffffffu, s, o);
        if (lane == 0) out[w] = 1.f / (1.f + __expf(-(s + bfc[0])));
    }
}

// ---------------- launch ----------------
extern "C" void kernel_launch(void* const* d_in, const int* in_sizes, int n_in,
                              void* d_out, int out_size) {
    const float* x    = (const float*)d_in[0];
    const float* wih0 = (const float*)d_in[1];
    const float* whh0 = (const float*)d_in[2];
    const float* bih0 = (const float*)d_in[3];
    const float* bhh0 = (const float*)d_in[4];
    const float* wih1 = (const float*)d_in[5];
    const float* whh1 = (const float*)d_in[6];
    const float* bih1 = (const float*)d_in[7];
    const float* bhh1 = (const float*)d_in[8];
    const float* wfc  = (const float*)d_in[9];
    const float* bfc  = (const float*)d_in[10];
    float* out = (float*)d_out;

    cudaFuncSetAttribute(k_lstm<0>, cudaFuncAttributeMaxDynamicSharedMemorySize, LSTM_SMEM);
    cudaFuncSetAttribute(k_lstm<1>, cudaFuncAttributeMaxDynamicSharedMemorySize, LSTM_SMEM);
    cudaFuncSetAttribute(k_gemm_xg<EE>, cudaFuncAttributeMaxDynamicSharedMemorySize, GEMM_SMEM);
    cudaFuncSetAttribute(k_gemm_xg<HH>, cudaFuncAttributeMaxDynamicSharedMemorySize, GEMM_SMEM);

    // prep: fp16 conversions + gate-column permutation
    k_conv_x<<<(MR * EE + 255) / 256, 256>>>(x);
    k_prep_w<<<dim3((GG * HH + 255) / 256, 4), 256>>>(wih0, whh0, wih1, whh1);
    k_prep_b<<<dim3((GG + 255) / 256, 2), 256>>>(bih0, bhh0, bih1, bhh1);

    // layer 1
    k_gemm_xg<EE><<<dim3(GG / 64, MR / 128), 256, GEMM_SMEM>>>(0);
    k_reset<<<256, 256>>>();
    k_lstm<0><<<NGROUP * NSLICE, 256, LSTM_SMEM>>>();

    // layer 2
    k_gemm_xg<HH><<<dim3(GG / 64, MR / 128), 256, GEMM_SMEM>>>(1);
    k_reset<<<256, 256>>>();
    k_lstm<1><<<NGROUP * NSLICE, 256, LSTM_SMEM>>>();

    // head
    k_fc<<<(BB + 3) / 4, 128>>>(wfc, bfc, out);
}